// round 1
// baseline (speedup 1.0000x reference)
#include <cuda_runtime.h>

#define D_DIM   128
#define K_RBF   64
#define TILE_E  256
#define GRP     8
#define THREADS 128

// stable shifted softplus: softplus(x) - ln(2)
__device__ __forceinline__ float ssp(float x) {
    return fmaxf(x, 0.f) + __logf(1.f + __expf(-fabsf(x))) - 0.69314718055994531f;
}

__global__ void zero_out_kernel(float* __restrict__ out, size_t n) {
    size_t i = (size_t)blockIdx.x * blockDim.x + threadIdx.x;
    size_t stride = (size_t)gridDim.x * blockDim.x;
    for (; i < n; i += stride) out[i] = 0.f;
}

extern __shared__ float smem[];

__global__ void __launch_bounds__(THREADS, 2)
cfconv_kernel(const float* __restrict__ AF,     // [B,N,D]
              const float* __restrict__ dist,   // [B,E]
              const int*   __restrict__ idx_j,  // [E]
              const int*   __restrict__ seg_i,  // [E] sorted
              const float* __restrict__ W1,     // [K,D]
              const float* __restrict__ b1,     // [D]
              const float* __restrict__ W2,     // [D,D]
              const float* __restrict__ b2,     // [D]
              const float* __restrict__ centers,// [K]
              const float* __restrict__ gamma,  // [K]
              float* __restrict__ out,          // [B,N,D]
              int B, int N, int E, int chunks_per_batch)
{
    float* W1s   = smem;                       // 64*128
    float* W2s   = W1s + K_RBF * D_DIM;        // 128*128
    float* b1s   = W2s + D_DIM * D_DIM;        // 128
    float* b2s   = b1s + D_DIM;                // 128
    float* cen_s = b2s + D_DIM;                // 64
    float* gam_s = cen_s + K_RBF;              // 64
    float* rbf_s = gam_s + K_RBF;              // GRP*64
    float* h1_s  = rbf_s + GRP * K_RBF;        // GRP*128

    const int tid = threadIdx.x;

    // Load weights once per CTA
    for (int i = tid; i < K_RBF * D_DIM; i += THREADS) W1s[i] = W1[i];
    for (int i = tid; i < D_DIM * D_DIM; i += THREADS) W2s[i] = W2[i];
    if (tid < D_DIM) { b1s[tid] = b1[tid]; b2s[tid] = b2[tid]; }
    if (tid < K_RBF) { cen_s[tid] = centers[tid]; gam_s[tid] = gamma[tid]; }
    __syncthreads();

    const int total_chunks = B * chunks_per_batch;
    for (int chunk = blockIdx.x; chunk < total_chunks; chunk += gridDim.x) {
        const int b  = chunk / chunks_per_batch;
        const int e0 = (chunk - b * chunks_per_batch) * TILE_E;
        const int n_e = min(TILE_E, E - e0);
        const int ng  = (n_e + GRP - 1) / GRP;

        const float* AFb  = AF  + (size_t)b * N * D_DIM;
        float*       outb = out + (size_t)b * N * D_DIM;
        const float* db   = dist + (size_t)b * E;

        int   cur   = -1;
        float accum = 0.f;

        for (int g = 0; g < ng; g++) {
            const int ge0 = e0 + g * GRP;
            __syncthreads();  // protect rbf_s / h1_s reuse across groups

            // -------- Phase A: RBF for GRP edges --------
            #pragma unroll
            for (int r = 0; r < (GRP * K_RBF) / THREADS; r++) {
                const int idx = tid + r * THREADS;
                const int el  = idx >> 6;     // edge within group
                const int k   = idx & 63;     // rbf index
                const int eg  = min(ge0 + el, E - 1);
                const float d = db[eg];
                const float t = d - cen_s[k];
                rbf_s[idx] = __expf(-gam_s[k] * t * t);
            }
            __syncthreads();

            // -------- Phase B: GEMM1 [GRP,64]x[64,128] + ssp --------
            float acc[GRP];
            #pragma unroll
            for (int e = 0; e < GRP; e++) acc[e] = b1s[tid];
            #pragma unroll 2
            for (int k = 0; k < K_RBF; k += 4) {
                const float w0 = W1s[(k + 0) * D_DIM + tid];
                const float w1 = W1s[(k + 1) * D_DIM + tid];
                const float w2 = W1s[(k + 2) * D_DIM + tid];
                const float w3 = W1s[(k + 3) * D_DIM + tid];
                #pragma unroll
                for (int e = 0; e < GRP; e++) {
                    const float4 rv = *reinterpret_cast<const float4*>(&rbf_s[e * K_RBF + k]);
                    acc[e] = fmaf(rv.x, w0, acc[e]);
                    acc[e] = fmaf(rv.y, w1, acc[e]);
                    acc[e] = fmaf(rv.z, w2, acc[e]);
                    acc[e] = fmaf(rv.w, w3, acc[e]);
                }
            }
            #pragma unroll
            for (int e = 0; e < GRP; e++) h1_s[e * D_DIM + tid] = ssp(acc[e]);
            __syncthreads();

            // -------- Phase C: GEMM2 [GRP,128]x[128,128] + ssp + gather + segsum --------
            #pragma unroll
            for (int e = 0; e < GRP; e++) acc[e] = b2s[tid];
            #pragma unroll 2
            for (int k = 0; k < D_DIM; k += 4) {
                const float w0 = W2s[(k + 0) * D_DIM + tid];
                const float w1 = W2s[(k + 1) * D_DIM + tid];
                const float w2 = W2s[(k + 2) * D_DIM + tid];
                const float w3 = W2s[(k + 3) * D_DIM + tid];
                #pragma unroll
                for (int e = 0; e < GRP; e++) {
                    const float4 hv = *reinterpret_cast<const float4*>(&h1_s[e * D_DIM + k]);
                    acc[e] = fmaf(hv.x, w0, acc[e]);
                    acc[e] = fmaf(hv.y, w1, acc[e]);
                    acc[e] = fmaf(hv.z, w2, acc[e]);
                    acc[e] = fmaf(hv.w, w3, acc[e]);
                }
            }

            #pragma unroll
            for (int e = 0; e < GRP; e++) {
                const int eg = ge0 + e;
                if (eg < e0 + n_e) {
                    const float filt = ssp(acc[e]);
                    const int j = __ldg(&idx_j[eg]);
                    const int s = __ldg(&seg_i[eg]);
                    const float msg = AFb[(size_t)j * D_DIM + tid] * filt;
                    if (s != cur) {
                        if (cur >= 0) atomicAdd(&outb[(size_t)cur * D_DIM + tid], accum);
                        cur = s;
                        accum = msg;
                    } else {
                        accum += msg;
                    }
                }
            }
        }
        if (cur >= 0) atomicAdd(&outb[(size_t)cur * D_DIM + tid], accum);
    }
}

extern "C" void kernel_launch(void* const* d_in, const int* in_sizes, int n_in,
                              void* d_out, int out_size) {
    // metadata order: atom_features, distances, idx_j, seg_i, centers, gamma, W1, b1, W2, b2
    const float* AF      = (const float*)d_in[0];
    const float* dist    = (const float*)d_in[1];
    const int*   idx_j   = (const int*)  d_in[2];
    const int*   seg_i   = (const int*)  d_in[3];
    const float* centers = (const float*)d_in[4];
    const float* gamma   = (const float*)d_in[5];
    const float* W1      = (const float*)d_in[6];
    const float* b1      = (const float*)d_in[7];
    const float* W2      = (const float*)d_in[8];
    const float* b2      = (const float*)d_in[9];
    float* out = (float*)d_out;

    const int E = in_sizes[2];
    const int B = in_sizes[1] / E;
    const int D = in_sizes[7];          // = 128
    const int N = in_sizes[0] / (B * D);
    const int chunks_per_batch = (E + TILE_E - 1) / TILE_E;

    // zero output (it is poisoned before timing)
    const size_t outn = (size_t)out_size;
    zero_out_kernel<<<2048, 256>>>(out, outn);

    const int smem_bytes = (K_RBF * D_DIM + D_DIM * D_DIM + 2 * D_DIM + 2 * K_RBF
                            + GRP * K_RBF + GRP * D_DIM) * (int)sizeof(float);
    cudaFuncSetAttribute(cfconv_kernel, cudaFuncAttributeMaxDynamicSharedMemorySize, smem_bytes);

    cfconv_kernel<<<296, THREADS, smem_bytes>>>(
        AF, dist, idx_j, seg_i, W1, b1, W2, b2, centers, gamma,
        out, B, N, E, chunks_per_batch);
}

// round 2
// speedup vs baseline: 2.5725x; 2.5725x over previous
#include <cuda_runtime.h>

#define D_DIM   128
#define K_RBF   64
#define CHUNK   512          // edges per chunk (per CTA work item)
#define SPAN    64           // CHUNK/8 contiguous edges per thread-group
#define ITERS   8            // SPAN/8 iterations per chunk
#define TILE    64           // edges processed per CTA iteration
#define THREADS 512

// stable shifted softplus: softplus(x) - ln(2)
__device__ __forceinline__ float ssp(float x) {
    return fmaxf(x, 0.f) + __logf(1.f + __expf(-fabsf(x))) - 0.69314718055994531f;
}

__global__ void zero_out_kernel(float* __restrict__ out, size_t n) {
    size_t i = (size_t)blockIdx.x * blockDim.x + threadIdx.x;
    size_t stride = (size_t)gridDim.x * blockDim.x;
    for (; i < n; i += stride) out[i] = 0.f;
}

extern __shared__ float smem[];

__global__ void __launch_bounds__(THREADS, 1)
cfconv_kernel(const float* __restrict__ AF,     // [B,N,D]
              const float* __restrict__ dist,   // [B,E]
              const int*   __restrict__ idx_j,  // [E]
              const int*   __restrict__ seg_i,  // [E] sorted
              const float* __restrict__ W1,     // [K,D]
              const float* __restrict__ b1,     // [D]
              const float* __restrict__ W2,     // [D,D]
              const float* __restrict__ b2,     // [D]
              const float* __restrict__ centers,// [K]
              const float* __restrict__ gamma,  // [K]
              float* __restrict__ out,          // [B,N,D]
              int B, int N, int E, int chunks_per_batch)
{
    float* W1s   = smem;                        // 64*128  = 8192
    float* W2s   = W1s + K_RBF * D_DIM;         // 128*128 = 16384
    float* b1s   = W2s + D_DIM * D_DIM;         // 128
    float* b2s   = b1s + D_DIM;                 // 128
    float* cen_s = b2s + D_DIM;                 // 64
    float* gam_s = cen_s + K_RBF;               // 64
    float* rbf_s = gam_s + K_RBF;               // TILE*64  = 4096
    float* h1_s  = rbf_s + TILE * K_RBF;        // TILE*128 = 8192

    const int tid = threadIdx.x;

    for (int i = tid; i < K_RBF * D_DIM; i += THREADS) W1s[i] = W1[i];
    for (int i = tid; i < D_DIM * D_DIM; i += THREADS) W2s[i] = W2[i];
    if (tid < D_DIM) { b1s[tid] = b1[tid]; b2s[tid] = b2[tid]; }
    else if (tid >= 256 && tid < 256 + K_RBF) {
        int k = tid - 256;
        cen_s[k] = centers[k]; gam_s[k] = gamma[k];
    }
    __syncthreads();

    const int p  = tid & 63;      // channel pair index (channels 2p, 2p+1)
    const int g  = tid >> 6;      // edge group 0..7
    const int c0 = 2 * p;

    const int total_chunks = B * chunks_per_batch;
    for (int chunk = blockIdx.x; chunk < total_chunks; chunk += gridDim.x) {
        const int b    = chunk / chunks_per_batch;
        const int base = (chunk - b * chunks_per_batch) * CHUNK;
        const int n_e  = min(CHUNK, E - base);

        const float* AFb  = AF  + (size_t)b * N * D_DIM;
        float*       outb = out + (size_t)b * N * D_DIM;
        const float* db   = dist + (size_t)b * E;

        int    cur   = -1;
        float2 accum = make_float2(0.f, 0.f);

        for (int it = 0; it < ITERS; it++) {
            // ---------------- Phase A: RBF for TILE edges ----------------
            #pragma unroll
            for (int i = 0; i < (TILE * K_RBF) / THREADS; i++) {
                const int idx = i * THREADS + tid;
                const int el  = idx >> 6;             // edge-local 0..63
                const int k   = idx & 63;
                int eg_local = (el >> 3) * SPAN + it * 8 + (el & 7);
                eg_local = min(eg_local, n_e - 1);    // clamp (harmless)
                const float d = __ldg(&db[base + eg_local]);
                const float t = d - cen_s[k];
                rbf_s[el * K_RBF + k] = __expf(-gam_s[k] * t * t);
            }
            __syncthreads();

            // ---------------- Phase B: GEMM1 (K=64) ----------------
            float a0[8], a1[8];
            {
                const float bb0 = b1s[c0], bb1 = b1s[c0 + 1];
                #pragma unroll
                for (int e = 0; e < 8; e++) { a0[e] = bb0; a1[e] = bb1; }
            }
            const float4* rbf4 = reinterpret_cast<const float4*>(rbf_s + g * 8 * K_RBF);
            #pragma unroll 2
            for (int k = 0; k < K_RBF; k += 4) {
                const float2 w0 = *reinterpret_cast<const float2*>(&W1s[(k + 0) * D_DIM + c0]);
                const float2 w1 = *reinterpret_cast<const float2*>(&W1s[(k + 1) * D_DIM + c0]);
                const float2 w2 = *reinterpret_cast<const float2*>(&W1s[(k + 2) * D_DIM + c0]);
                const float2 w3 = *reinterpret_cast<const float2*>(&W1s[(k + 3) * D_DIM + c0]);
                #pragma unroll
                for (int e = 0; e < 8; e++) {
                    const float4 r = rbf4[e * (K_RBF / 4) + (k >> 2)];
                    a0[e] = fmaf(r.x, w0.x, a0[e]); a1[e] = fmaf(r.x, w0.y, a1[e]);
                    a0[e] = fmaf(r.y, w1.x, a0[e]); a1[e] = fmaf(r.y, w1.y, a1[e]);
                    a0[e] = fmaf(r.z, w2.x, a0[e]); a1[e] = fmaf(r.z, w2.y, a1[e]);
                    a0[e] = fmaf(r.w, w3.x, a0[e]); a1[e] = fmaf(r.w, w3.y, a1[e]);
                }
            }
            #pragma unroll
            for (int e = 0; e < 8; e++) {
                *reinterpret_cast<float2*>(&h1_s[(g * 8 + e) * D_DIM + c0]) =
                    make_float2(ssp(a0[e]), ssp(a1[e]));
            }
            __syncthreads();

            // ---------------- Phase C: GEMM2 (K=128) ----------------
            {
                const float bb0 = b2s[c0], bb1 = b2s[c0 + 1];
                #pragma unroll
                for (int e = 0; e < 8; e++) { a0[e] = bb0; a1[e] = bb1; }
            }
            const float4* h14 = reinterpret_cast<const float4*>(h1_s + g * 8 * D_DIM);
            #pragma unroll 2
            for (int k = 0; k < D_DIM; k += 4) {
                const float2 w0 = *reinterpret_cast<const float2*>(&W2s[(k + 0) * D_DIM + c0]);
                const float2 w1 = *reinterpret_cast<const float2*>(&W2s[(k + 1) * D_DIM + c0]);
                const float2 w2 = *reinterpret_cast<const float2*>(&W2s[(k + 2) * D_DIM + c0]);
                const float2 w3 = *reinterpret_cast<const float2*>(&W2s[(k + 3) * D_DIM + c0]);
                #pragma unroll
                for (int e = 0; e < 8; e++) {
                    const float4 h = h14[e * (D_DIM / 4) + (k >> 2)];
                    a0[e] = fmaf(h.x, w0.x, a0[e]); a1[e] = fmaf(h.x, w0.y, a1[e]);
                    a0[e] = fmaf(h.y, w1.x, a0[e]); a1[e] = fmaf(h.y, w1.y, a1[e]);
                    a0[e] = fmaf(h.z, w2.x, a0[e]); a1[e] = fmaf(h.z, w2.y, a1[e]);
                    a0[e] = fmaf(h.w, w3.x, a0[e]); a1[e] = fmaf(h.w, w3.y, a1[e]);
                }
            }

            // ------- Phase D: ssp, gather, sorted segment accumulate -------
            #pragma unroll
            for (int e = 0; e < 8; e++) {
                const int eg_local = g * SPAN + it * 8 + e;
                if (eg_local < n_e) {
                    const int eg = base + eg_local;
                    const float f0 = ssp(a0[e]);
                    const float f1 = ssp(a1[e]);
                    const int j = __ldg(&idx_j[eg]);
                    const int s = __ldg(&seg_i[eg]);
                    const float2 af = *reinterpret_cast<const float2*>(&AFb[(size_t)j * D_DIM + c0]);
                    if (s != cur) {
                        if (cur >= 0) {
                            atomicAdd(&outb[(size_t)cur * D_DIM + c0],     accum.x);
                            atomicAdd(&outb[(size_t)cur * D_DIM + c0 + 1], accum.y);
                        }
                        cur = s;
                        accum = make_float2(af.x * f0, af.y * f1);
                    } else {
                        accum.x = fmaf(af.x, f0, accum.x);
                        accum.y = fmaf(af.y, f1, accum.y);
                    }
                }
            }
        }

        // flush at chunk end (batch/base changes next chunk)
        if (cur >= 0) {
            atomicAdd(&outb[(size_t)cur * D_DIM + c0],     accum.x);
            atomicAdd(&outb[(size_t)cur * D_DIM + c0 + 1], accum.y);
            cur = -1;
            accum = make_float2(0.f, 0.f);
        }
    }
}

extern "C" void kernel_launch(void* const* d_in, const int* in_sizes, int n_in,
                              void* d_out, int out_size) {
    // metadata order: atom_features, distances, idx_j, seg_i, centers, gamma, W1, b1, W2, b2
    const float* AF      = (const float*)d_in[0];
    const float* dist    = (const float*)d_in[1];
    const int*   idx_j   = (const int*)  d_in[2];
    const int*   seg_i   = (const int*)  d_in[3];
    const float* centers = (const float*)d_in[4];
    const float* gamma   = (const float*)d_in[5];
    const float* W1      = (const float*)d_in[6];
    const float* b1      = (const float*)d_in[7];
    const float* W2      = (const float*)d_in[8];
    const float* b2      = (const float*)d_in[9];
    float* out = (float*)d_out;

    const int E = in_sizes[2];
    const int B = in_sizes[1] / E;
    const int D = in_sizes[7];          // = 128
    const int N = in_sizes[0] / (B * D);
    const int chunks_per_batch = (E + CHUNK - 1) / CHUNK;

    zero_out_kernel<<<2048, 256>>>(out, (size_t)out_size);

    const int smem_bytes = (K_RBF * D_DIM + D_DIM * D_DIM + 2 * D_DIM + 2 * K_RBF
                            + TILE * K_RBF + TILE * D_DIM) * (int)sizeof(float);
    cudaFuncSetAttribute(cfconv_kernel, cudaFuncAttributeMaxDynamicSharedMemorySize, smem_bytes);

    cfconv_kernel<<<148, THREADS, smem_bytes>>>(
        AF, dist, idx_j, seg_i, W1, b1, W2, b2, centers, gamma,
        out, B, N, E, chunks_per_batch);
}

// round 4
// speedup vs baseline: 3.1618x; 1.2291x over previous
#include <cuda_runtime.h>
#include <cuda_bf16.h>
#include <cstdint>

#define THREADS 256
#define TILE_M  128
#define D_DIM   128
#define K_RBF   64

// strides in elements
#define W_STR   136      // bf16 halves per weight row (128 + 8 pad) -> 272B, 16B-mult
#define A1_STR  72       // bf16 halves per A1 row (64 + 8 pad) -> 144B
#define A2_STR  136
#define FB_STR  130      // floats per fbuf row (128 + 2 pad), even for float2

// ---------------- smem layout (bytes) ----------------
#define OFF_W1HI 0
#define OFF_W1LO (OFF_W1HI + K_RBF * W_STR * 2)       // 17408
#define OFF_W2HI (OFF_W1LO + K_RBF * W_STR * 2)       // 34816
#define OFF_W2LO (OFF_W2HI + D_DIM * W_STR * 2)       // 69632
#define OFF_A1HI (OFF_W2LO + D_DIM * W_STR * 2)       // 104448
#define OFF_A1LO (OFF_A1HI + TILE_M * A1_STR * 2)     // 122880
#define OFF_A2HI (OFF_A1LO + TILE_M * A1_STR * 2)     // 141312
#define OFF_A2LO (OFF_A2HI + TILE_M * A2_STR * 2)     // 176128
#define OFF_FBUF OFF_A1HI                              // overlay (guarded by syncs)
#define OFF_B1S  (OFF_A2LO + TILE_M * A2_STR * 2)     // 210944
#define OFF_B2S  (OFF_B1S + 512)
#define OFF_CEN  (OFF_B2S + 512)
#define OFF_GAM  (OFF_CEN + 256)
#define OFF_EJ   (OFF_GAM + 256)
#define OFF_ES   (OFF_EJ + 512)
#define SMEM_TOTAL (OFF_ES + 512)                      // 213504

// ---------------- PTX helpers ----------------
static __device__ __forceinline__ uint32_t smem_u32(const void* p) {
    uint32_t a;
    asm("{ .reg .u64 t; cvta.to.shared.u64 t, %1; cvt.u32.u64 %0, t; }" : "=r"(a) : "l"(p));
    return a;
}

#define LDSM_X4(r, addr)                                                     \
    asm volatile("ldmatrix.sync.aligned.m8n8.x4.shared.b16 {%0,%1,%2,%3}, [%4];" \
        : "=r"((r)[0]), "=r"((r)[1]), "=r"((r)[2]), "=r"((r)[3]) : "r"(addr))

#define LDSM_X2T(r, addr)                                                    \
    asm volatile("ldmatrix.sync.aligned.m8n8.x2.trans.shared.b16 {%0,%1}, [%2];" \
        : "=r"((r)[0]), "=r"((r)[1]) : "r"(addr))

#define MMA_BF16(c, a, b)                                                    \
    asm volatile("mma.sync.aligned.m16n8k16.row.col.f32.bf16.bf16.f32 "     \
        "{%0,%1,%2,%3}, {%4,%5,%6,%7}, {%8,%9}, {%0,%1,%2,%3};"             \
        : "+f"((c)[0]), "+f"((c)[1]), "+f"((c)[2]), "+f"((c)[3])            \
        : "r"((a)[0]), "r"((a)[1]), "r"((a)[2]), "r"((a)[3]),               \
          "r"((b)[0]), "r"((b)[1]))

static __device__ __forceinline__ float ssp(float x) {
    return fmaxf(x, 0.f) + __logf(1.f + __expf(-fabsf(x))) - 0.69314718055994531f;
}

static __device__ __forceinline__ void bf16_split(float f, uint16_t& hi, uint16_t& lo) {
    __nv_bfloat16 h = __float2bfloat16(f);
    float r = f - __bfloat162float(h);
    __nv_bfloat16 l = __float2bfloat16(r);
    hi = *reinterpret_cast<uint16_t*>(&h);
    lo = *reinterpret_cast<uint16_t*>(&l);
}

__global__ void zero_out_kernel(float* __restrict__ out, size_t n) {
    size_t i = (size_t)blockIdx.x * blockDim.x + threadIdx.x;
    size_t stride = (size_t)gridDim.x * blockDim.x;
    for (; i < n; i += stride) out[i] = 0.f;
}

extern __shared__ char smem[];

__global__ void __launch_bounds__(THREADS, 1)
cfconv_mma_kernel(const float* __restrict__ AF,     // [B,N,D]
                  const float* __restrict__ dist,   // [B,E]
                  const int*   __restrict__ idx_j,  // [E]
                  const int*   __restrict__ seg_i,  // [E] sorted
                  const float* __restrict__ W1,     // [K,D]
                  const float* __restrict__ b1,
                  const float* __restrict__ W2,     // [D,D]
                  const float* __restrict__ b2,
                  const float* __restrict__ centers,
                  const float* __restrict__ gamma,
                  float* __restrict__ out,          // [B,N,D]
                  int B, int N, int E)
{
    const uint32_t sb = smem_u32(smem);
    const int tid  = threadIdx.x;
    const int w    = tid >> 5;
    const int lane = tid & 31;

    float* b1s = (float*)(smem + OFF_B1S);
    float* b2s = (float*)(smem + OFF_B2S);
    float* cen = (float*)(smem + OFF_CEN);
    float* gam = (float*)(smem + OFF_GAM);
    int*   ejs = (int*)  (smem + OFF_EJ);
    int*   ess = (int*)  (smem + OFF_ES);
    float* fb  = (float*)(smem + OFF_FBUF);

    // ---- weight prep: bf16 hi/lo, padded row-major [K][D] ----
    for (int i = tid; i < K_RBF * D_DIM; i += THREADS) {
        const int k = i >> 7, d = i & 127;
        uint16_t hi, lo; bf16_split(W1[i], hi, lo);
        *(uint16_t*)(smem + OFF_W1HI + (k * W_STR + d) * 2) = hi;
        *(uint16_t*)(smem + OFF_W1LO + (k * W_STR + d) * 2) = lo;
    }
    for (int i = tid; i < D_DIM * D_DIM; i += THREADS) {
        const int k = i >> 7, d = i & 127;
        uint16_t hi, lo; bf16_split(W2[i], hi, lo);
        *(uint16_t*)(smem + OFF_W2HI + (k * W_STR + d) * 2) = hi;
        *(uint16_t*)(smem + OFF_W2LO + (k * W_STR + d) * 2) = lo;
    }
    if (tid < D_DIM) { b1s[tid] = b1[tid]; b2s[tid] = b2[tid]; }
    if (tid >= 128 && tid < 128 + K_RBF) {
        const int k = tid - 128; cen[k] = centers[k]; gam[k] = gamma[k];
    }
    __syncthreads();

    const int m0 = w * 16;
    const int arow = lane & 15;
    const int acol = (lane >> 4) * 8;
    const int gr   = lane >> 2;          // C-frag row within 0..7
    const int cc   = (lane & 3) * 2;     // C-frag col pair base

    const int tiles_pb = (E + TILE_M - 1) / TILE_M;
    const int total    = B * tiles_pb;

    for (int g = blockIdx.x; g < total; g += gridDim.x) {
        const int b  = g / tiles_pb;
        const int e0 = (g - b * tiles_pb) * TILE_M;
        const int ne = min(TILE_M, E - e0);
        const float* db = dist + (size_t)b * E;

        // -------- Phase A: RBF -> A1 (bf16 hi/lo), meta --------
        {
            const int el = tid >> 1;
            const int k0 = (tid & 1) * 32;
            const int eg = e0 + min(el, ne - 1);
            const float dv = __ldg(&db[eg]);
            #pragma unroll
            for (int kk = 0; kk < 32; kk += 2) {
                const int k = k0 + kk;
                const float t0 = dv - cen[k];
                const float t1 = dv - cen[k + 1];
                const float r0 = __expf(-gam[k]     * t0 * t0);
                const float r1 = __expf(-gam[k + 1] * t1 * t1);
                uint16_t h0, l0, h1, l1;
                bf16_split(r0, h0, l0);
                bf16_split(r1, h1, l1);
                const uint32_t byt = (uint32_t)(el * A1_STR + k) * 2;
                *(uint32_t*)(smem + OFF_A1HI + byt) = ((uint32_t)h1 << 16) | h0;
                *(uint32_t*)(smem + OFF_A1LO + byt) = ((uint32_t)l1 << 16) | l0;
            }
            if (tid < TILE_M) {
                const int e = e0 + min(tid, ne - 1);
                ejs[tid] = __ldg(&idx_j[e]);
                ess[tid] = __ldg(&seg_i[e]);
            }
        }
        __syncthreads();

        float c[16][4];
        #pragma unroll
        for (int n = 0; n < 16; n++)
            { c[n][0] = 0.f; c[n][1] = 0.f; c[n][2] = 0.f; c[n][3] = 0.f; }

        // -------- GEMM1: [128x64] x W1 -> [128x128] --------
        #pragma unroll
        for (int k = 0; k < 4; k++) {
            uint32_t ah[4], al[4];
            const uint32_t abyt = (uint32_t)((m0 + arow) * A1_STR + k * 16 + acol) * 2;
            LDSM_X4(ah, sb + OFF_A1HI + abyt);
            LDSM_X4(al, sb + OFF_A1LO + abyt);
            const uint32_t brow = (uint32_t)((k * 16 + arow) * W_STR) * 2;
            #pragma unroll
            for (int n = 0; n < 16; n++) {
                uint32_t bh[2], bl[2];
                const uint32_t bbyt = brow + n * 16;
                LDSM_X2T(bh, sb + OFF_W1HI + bbyt);
                LDSM_X2T(bl, sb + OFF_W1LO + bbyt);
                MMA_BF16(c[n], ah, bh);
                MMA_BF16(c[n], al, bh);
                MMA_BF16(c[n], ah, bl);
            }
        }

        // -------- Epilogue 1: +b1, ssp, split -> A2 --------
        #pragma unroll
        for (int n = 0; n < 16; n++) {
            const int col = n * 8 + cc;
            const float f0 = ssp(c[n][0] + b1s[col]);
            const float f1 = ssp(c[n][1] + b1s[col + 1]);
            const float f2 = ssp(c[n][2] + b1s[col]);
            const float f3 = ssp(c[n][3] + b1s[col + 1]);
            uint16_t h0, l0, h1, l1, h2, l2, h3, l3;
            bf16_split(f0, h0, l0); bf16_split(f1, h1, l1);
            bf16_split(f2, h2, l2); bf16_split(f3, h3, l3);
            const uint32_t r0b = (uint32_t)((m0 + gr)     * A2_STR + col) * 2;
            const uint32_t r1b = (uint32_t)((m0 + gr + 8) * A2_STR + col) * 2;
            *(uint32_t*)(smem + OFF_A2HI + r0b) = ((uint32_t)h1 << 16) | h0;
            *(uint32_t*)(smem + OFF_A2LO + r0b) = ((uint32_t)l1 << 16) | l0;
            *(uint32_t*)(smem + OFF_A2HI + r1b) = ((uint32_t)h3 << 16) | h2;
            *(uint32_t*)(smem + OFF_A2LO + r1b) = ((uint32_t)l3 << 16) | l2;
            c[n][0] = 0.f; c[n][1] = 0.f; c[n][2] = 0.f; c[n][3] = 0.f;
        }
        __syncthreads();

        // -------- GEMM2: [128x128] x W2 -> [128x128] --------
        #pragma unroll
        for (int k = 0; k < 8; k++) {
            uint32_t ah[4], al[4];
            const uint32_t abyt = (uint32_t)((m0 + arow) * A2_STR + k * 16 + acol) * 2;
            LDSM_X4(ah, sb + OFF_A2HI + abyt);
            LDSM_X4(al, sb + OFF_A2LO + abyt);
            const uint32_t brow = (uint32_t)((k * 16 + arow) * W_STR) * 2;
            #pragma unroll
            for (int n = 0; n < 16; n++) {
                uint32_t bh[2], bl[2];
                const uint32_t bbyt = brow + n * 16;
                LDSM_X2T(bh, sb + OFF_W2HI + bbyt);
                LDSM_X2T(bl, sb + OFF_W2LO + bbyt);
                MMA_BF16(c[n], ah, bh);
                MMA_BF16(c[n], al, bh);
                MMA_BF16(c[n], ah, bl);
            }
        }
        __syncthreads();   // all warps done reading A2 before fbuf overlay writes

        // -------- Epilogue 2: +b2, ssp -> fbuf (fp32) --------
        #pragma unroll
        for (int n = 0; n < 16; n++) {
            const int col = n * 8 + cc;
            const float f0 = ssp(c[n][0] + b2s[col]);
            const float f1 = ssp(c[n][1] + b2s[col + 1]);
            const float f2 = ssp(c[n][2] + b2s[col]);
            const float f3 = ssp(c[n][3] + b2s[col + 1]);
            *(float2*)&fb[(m0 + gr)     * FB_STR + col] = make_float2(f0, f1);
            *(float2*)&fb[(m0 + gr + 8) * FB_STR + col] = make_float2(f2, f3);
        }
        __syncthreads();

        // -------- Gather + sorted segment-sum --------
        {
            const int ch = tid & 127;
            const int sp = tid >> 7;
            const float* AFp = AF + (size_t)b * N * D_DIM;
            float*       Op  = out + (size_t)b * N * D_DIM;
            int cur = -1; float acc = 0.f;
            const int e_beg = sp * 64;
            const int e_end = min(e_beg + 64, ne);
            for (int e = e_beg; e < e_end; e++) {
                const float f = fb[e * FB_STR + ch];
                const int j = ejs[e];
                const int s = ess[e];
                const float m = __ldg(&AFp[(size_t)j * D_DIM + ch]) * f;
                if (s != cur) {
                    if (cur >= 0) atomicAdd(&Op[(size_t)cur * D_DIM + ch], acc);
                    cur = s; acc = m;
                } else acc += m;
            }
            if (cur >= 0) atomicAdd(&Op[(size_t)cur * D_DIM + ch], acc);
        }
        __syncthreads();   // fbuf free before next tile's A1 writes (overlay)
    }
}

extern "C" void kernel_launch(void* const* d_in, const int* in_sizes, int n_in,
                              void* d_out, int out_size) {
    // order: atom_features, distances, idx_j, seg_i, centers, gamma, W1, b1, W2, b2
    const float* AF      = (const float*)d_in[0];
    const float* dist    = (const float*)d_in[1];
    const int*   idx_j   = (const int*)  d_in[2];
    const int*   seg_i   = (const int*)  d_in[3];
    const float* centers = (const float*)d_in[4];
    const float* gamma   = (const float*)d_in[5];
    const float* W1      = (const float*)d_in[6];
    const float* b1      = (const float*)d_in[7];
    const float* W2      = (const float*)d_in[8];
    const float* b2      = (const float*)d_in[9];
    float* out = (float*)d_out;

    const int E = in_sizes[2];
    const int B = in_sizes[1] / E;
    const int D = in_sizes[7];              // 128
    const int N = in_sizes[0] / (B * D);

    zero_out_kernel<<<2048, 256>>>(out, (size_t)out_size);

    cudaFuncSetAttribute(cfconv_mma_kernel,
                         cudaFuncAttributeMaxDynamicSharedMemorySize, SMEM_TOTAL);
    cfconv_mma_kernel<<<148, THREADS, SMEM_TOTAL>>>(
        AF, dist, idx_j, seg_i, W1, b1, W2, b2, centers, gamma, out, B, N, E);
}

// round 5
// speedup vs baseline: 4.5134x; 1.4275x over previous
#include <cuda_runtime.h>
#include <cuda_bf16.h>
#include <cstdint>

#define THREADS 512
#define TILE_M  128
#define D_DIM   128
#define K_RBF   64

// strides in bf16 elements
#define W_STR   136      // 128 + 8 pad
#define A1_STR  72       // 64 + 8 pad
#define A2_STR  136
#define FB_STR  130      // floats per fbuf row

// ---------------- smem layout (bytes) ----------------
#define OFF_W1HI 0
#define OFF_W1LO (OFF_W1HI + K_RBF * W_STR * 2)       // 17408
#define OFF_W2HI (OFF_W1LO + K_RBF * W_STR * 2)       // 34816
#define OFF_W2LO (OFF_W2HI + D_DIM * W_STR * 2)       // 69632
#define OFF_A1HI (OFF_W2LO + D_DIM * W_STR * 2)       // 104448
#define OFF_A1LO (OFF_A1HI + TILE_M * A1_STR * 2)     // 122880
#define OFF_A2HI (OFF_A1LO + TILE_M * A1_STR * 2)     // 141312
#define OFF_A2LO (OFF_A2HI + TILE_M * A2_STR * 2)     // 176128
#define OFF_FBUF OFF_A1HI                              // overlay (guarded by syncs)
#define OFF_B1S  (OFF_A2LO + TILE_M * A2_STR * 2)     // 210944
#define OFF_B2S  (OFF_B1S + 512)
#define OFF_CEN  (OFF_B2S + 512)
#define OFF_GAM  (OFF_CEN + 256)
#define OFF_EJ   (OFF_GAM + 256)
#define OFF_ES   (OFF_EJ + 512)
#define SMEM_TOTAL (OFF_ES + 512)                      // 213504

// ---------------- PTX helpers ----------------
static __device__ __forceinline__ uint32_t smem_u32(const void* p) {
    uint32_t a;
    asm("{ .reg .u64 t; cvta.to.shared.u64 t, %1; cvt.u32.u64 %0, t; }" : "=r"(a) : "l"(p));
    return a;
}

#define LDSM_X4(r, addr)                                                     \
    asm volatile("ldmatrix.sync.aligned.m8n8.x4.shared.b16 {%0,%1,%2,%3}, [%4];" \
        : "=r"((r)[0]), "=r"((r)[1]), "=r"((r)[2]), "=r"((r)[3]) : "r"(addr))

#define LDSM_X2T(r, addr)                                                    \
    asm volatile("ldmatrix.sync.aligned.m8n8.x2.trans.shared.b16 {%0,%1}, [%2];" \
        : "=r"((r)[0]), "=r"((r)[1]) : "r"(addr))

#define MMA_BF16(c, a, b)                                                    \
    asm volatile("mma.sync.aligned.m16n8k16.row.col.f32.bf16.bf16.f32 "     \
        "{%0,%1,%2,%3}, {%4,%5,%6,%7}, {%8,%9}, {%0,%1,%2,%3};"             \
        : "+f"((c)[0]), "+f"((c)[1]), "+f"((c)[2]), "+f"((c)[3])            \
        : "r"((a)[0]), "r"((a)[1]), "r"((a)[2]), "r"((a)[3]),               \
          "r"((b)[0]), "r"((b)[1]))

static __device__ __forceinline__ float ssp(float x) {
    return fmaxf(x, 0.f) + __logf(1.f + __expf(-fabsf(x))) - 0.69314718055994531f;
}

static __device__ __forceinline__ void bf16_split(float f, uint16_t& hi, uint16_t& lo) {
    __nv_bfloat16 h = __float2bfloat16(f);
    float r = f - __bfloat162float(h);
    __nv_bfloat16 l = __float2bfloat16(r);
    hi = *reinterpret_cast<uint16_t*>(&h);
    lo = *reinterpret_cast<uint16_t*>(&l);
}

__global__ void zero_out_kernel(float* __restrict__ out, size_t n) {
    size_t i = (size_t)blockIdx.x * blockDim.x + threadIdx.x;
    size_t stride = (size_t)gridDim.x * blockDim.x;
    for (; i < n; i += stride) out[i] = 0.f;
}

extern __shared__ char smem[];

__global__ void __launch_bounds__(THREADS, 1)
cfconv_mma_kernel(const float* __restrict__ AF,     // [B,N,D]
                  const float* __restrict__ dist,   // [B,E]
                  const int*   __restrict__ idx_j,  // [E]
                  const int*   __restrict__ seg_i,  // [E] sorted
                  const float* __restrict__ W1,     // [K,D]
                  const float* __restrict__ b1,
                  const float* __restrict__ W2,     // [D,D]
                  const float* __restrict__ b2,
                  const float* __restrict__ centers,
                  const float* __restrict__ gamma,
                  float* __restrict__ out,          // [B,N,D]
                  int B, int N, int E)
{
    const uint32_t sb = smem_u32(smem);
    const int tid  = threadIdx.x;
    const int w    = tid >> 5;
    const int lane = tid & 31;

    float* b1s = (float*)(smem + OFF_B1S);
    float* b2s = (float*)(smem + OFF_B2S);
    float* cen = (float*)(smem + OFF_CEN);
    float* gam = (float*)(smem + OFF_GAM);
    int*   ejs = (int*)  (smem + OFF_EJ);
    int*   ess = (int*)  (smem + OFF_ES);
    float* fb  = (float*)(smem + OFF_FBUF);

    // ---- weight prep: bf16 hi/lo, padded row-major [K][D] ----
    for (int i = tid; i < K_RBF * D_DIM; i += THREADS) {
        const int k = i >> 7, d = i & 127;
        uint16_t hi, lo; bf16_split(W1[i], hi, lo);
        *(uint16_t*)(smem + OFF_W1HI + (k * W_STR + d) * 2) = hi;
        *(uint16_t*)(smem + OFF_W1LO + (k * W_STR + d) * 2) = lo;
    }
    for (int i = tid; i < D_DIM * D_DIM; i += THREADS) {
        const int k = i >> 7, d = i & 127;
        uint16_t hi, lo; bf16_split(W2[i], hi, lo);
        *(uint16_t*)(smem + OFF_W2HI + (k * W_STR + d) * 2) = hi;
        *(uint16_t*)(smem + OFF_W2LO + (k * W_STR + d) * 2) = lo;
    }
    if (tid < D_DIM) { b1s[tid] = b1[tid]; b2s[tid] = b2[tid]; }
    if (tid >= 128 && tid < 128 + K_RBF) {
        const int k = tid - 128; cen[k] = centers[k]; gam[k] = gamma[k];
    }
    __syncthreads();

    // warp tiling: 4x4 warp grid, each warp owns 32 edges x 32 cols
    const int wm = w & 3;              // row group
    const int wn = w >> 2;             // col group
    const int r0 = wm * 32;            // edge-row base
    const int d0 = wn * 32;            // col base
    const int arow = lane & 15;
    const int acol = (lane >> 4) * 8;
    const int gr   = lane >> 2;        // C-frag row 0..7
    const int cc   = (lane & 3) * 2;   // C-frag col pair

    const int tiles_pb = (E + TILE_M - 1) / TILE_M;
    const int total    = B * tiles_pb;

    for (int g = blockIdx.x; g < total; g += gridDim.x) {
        const int b  = g / tiles_pb;
        const int e0 = (g - b * tiles_pb) * TILE_M;
        const int ne = min(TILE_M, E - e0);
        const float* db = dist + (size_t)b * E;

        // -------- Phase A: RBF -> A1 (bf16 hi/lo), meta --------
        {
            const int el = tid >> 2;              // edge 0..127
            const int k0 = (tid & 3) * 16;        // 16 rbf per thread
            const int eg = e0 + min(el, ne - 1);
            const float dv = __ldg(&db[eg]);
            #pragma unroll
            for (int kk = 0; kk < 16; kk += 2) {
                const int k = k0 + kk;
                const float t0 = dv - cen[k];
                const float t1 = dv - cen[k + 1];
                const float v0 = __expf(-gam[k]     * t0 * t0);
                const float v1 = __expf(-gam[k + 1] * t1 * t1);
                uint16_t h0, l0, h1, l1;
                bf16_split(v0, h0, l0);
                bf16_split(v1, h1, l1);
                const uint32_t byt = (uint32_t)(el * A1_STR + k) * 2;
                *(uint32_t*)(smem + OFF_A1HI + byt) = ((uint32_t)h1 << 16) | h0;
                *(uint32_t*)(smem + OFF_A1LO + byt) = ((uint32_t)l1 << 16) | l0;
            }
            if (tid < TILE_M) {
                const int e = e0 + min(tid, ne - 1);
                ejs[tid] = __ldg(&idx_j[e]);
                ess[tid] = __ldg(&seg_i[e]);
            }
        }
        __syncthreads();

        float c[2][4][4];
        #pragma unroll
        for (int mt = 0; mt < 2; mt++)
            #pragma unroll
            for (int nt = 0; nt < 4; nt++)
                { c[mt][nt][0]=0.f; c[mt][nt][1]=0.f; c[mt][nt][2]=0.f; c[mt][nt][3]=0.f; }

        // -------- GEMM1: [32x64] x W1[:,d0:d0+32] --------
        #pragma unroll
        for (int k = 0; k < 4; k++) {
            uint32_t ah[2][4], al[2][4];
            #pragma unroll
            for (int mt = 0; mt < 2; mt++) {
                const uint32_t ab = (uint32_t)((r0 + mt*16 + arow) * A1_STR + k*16 + acol) * 2;
                LDSM_X4(ah[mt], sb + OFF_A1HI + ab);
                LDSM_X4(al[mt], sb + OFF_A1LO + ab);
            }
            const uint32_t brow = (uint32_t)((k*16 + arow) * W_STR) * 2;
            #pragma unroll
            for (int nt = 0; nt < 4; nt++) {
                uint32_t bh[2], bl[2];
                const uint32_t bb = brow + (uint32_t)(d0 + nt*8) * 2;
                LDSM_X2T(bh, sb + OFF_W1HI + bb);
                LDSM_X2T(bl, sb + OFF_W1LO + bb);
                #pragma unroll
                for (int mt = 0; mt < 2; mt++) {
                    MMA_BF16(c[mt][nt], ah[mt], bh);
                    MMA_BF16(c[mt][nt], al[mt], bh);
                    MMA_BF16(c[mt][nt], ah[mt], bl);
                }
            }
        }

        // -------- Epilogue 1: +b1, ssp, split -> A2 --------
        #pragma unroll
        for (int mt = 0; mt < 2; mt++) {
            #pragma unroll
            for (int nt = 0; nt < 4; nt++) {
                const int col = d0 + nt*8 + cc;
                const float f0 = ssp(c[mt][nt][0] + b1s[col]);
                const float f1 = ssp(c[mt][nt][1] + b1s[col + 1]);
                const float f2 = ssp(c[mt][nt][2] + b1s[col]);
                const float f3 = ssp(c[mt][nt][3] + b1s[col + 1]);
                uint16_t h0,l0,h1,l1,h2,l2,h3,l3;
                bf16_split(f0,h0,l0); bf16_split(f1,h1,l1);
                bf16_split(f2,h2,l2); bf16_split(f3,h3,l3);
                const uint32_t r0b = (uint32_t)((r0 + mt*16 + gr)     * A2_STR + col) * 2;
                const uint32_t r1b = (uint32_t)((r0 + mt*16 + gr + 8) * A2_STR + col) * 2;
                *(uint32_t*)(smem + OFF_A2HI + r0b) = ((uint32_t)h1 << 16) | h0;
                *(uint32_t*)(smem + OFF_A2LO + r0b) = ((uint32_t)l1 << 16) | l0;
                *(uint32_t*)(smem + OFF_A2HI + r1b) = ((uint32_t)h3 << 16) | h2;
                *(uint32_t*)(smem + OFF_A2LO + r1b) = ((uint32_t)l3 << 16) | l2;
                c[mt][nt][0]=0.f; c[mt][nt][1]=0.f; c[mt][nt][2]=0.f; c[mt][nt][3]=0.f;
            }
        }
        __syncthreads();

        // -------- GEMM2: [32x128] x W2[:,d0:d0+32] --------
        #pragma unroll
        for (int k = 0; k < 8; k++) {
            uint32_t ah[2][4], al[2][4];
            #pragma unroll
            for (int mt = 0; mt < 2; mt++) {
                const uint32_t ab = (uint32_t)((r0 + mt*16 + arow) * A2_STR + k*16 + acol) * 2;
                LDSM_X4(ah[mt], sb + OFF_A2HI + ab);
                LDSM_X4(al[mt], sb + OFF_A2LO + ab);
            }
            const uint32_t brow = (uint32_t)((k*16 + arow) * W_STR) * 2;
            #pragma unroll
            for (int nt = 0; nt < 4; nt++) {
                uint32_t bh[2], bl[2];
                const uint32_t bb = brow + (uint32_t)(d0 + nt*8) * 2;
                LDSM_X2T(bh, sb + OFF_W2HI + bb);
                LDSM_X2T(bl, sb + OFF_W2LO + bb);
                #pragma unroll
                for (int mt = 0; mt < 2; mt++) {
                    MMA_BF16(c[mt][nt], ah[mt], bh);
                    MMA_BF16(c[mt][nt], al[mt], bh);
                    MMA_BF16(c[mt][nt], ah[mt], bl);
                }
            }
        }
        __syncthreads();   // all warps done with A1/A2 before fbuf overlay writes

        // -------- Epilogue 2: +b2, ssp -> fbuf (fp32) --------
        #pragma unroll
        for (int mt = 0; mt < 2; mt++) {
            #pragma unroll
            for (int nt = 0; nt < 4; nt++) {
                const int col = d0 + nt*8 + cc;
                const float f0 = ssp(c[mt][nt][0] + b2s[col]);
                const float f1 = ssp(c[mt][nt][1] + b2s[col + 1]);
                const float f2 = ssp(c[mt][nt][2] + b2s[col]);
                const float f3 = ssp(c[mt][nt][3] + b2s[col + 1]);
                *(float2*)&fb[(r0 + mt*16 + gr)     * FB_STR + col] = make_float2(f0, f1);
                *(float2*)&fb[(r0 + mt*16 + gr + 8) * FB_STR + col] = make_float2(f2, f3);
            }
        }
        __syncthreads();

        // -------- Gather + sorted segment-sum (4 spans x 128 ch) --------
        {
            const int ch = tid & 127;
            const int sp = tid >> 7;            // 0..3
            const float* AFp = AF + (size_t)b * N * D_DIM;
            float*       Op  = out + (size_t)b * N * D_DIM;
            int cur = -1; float acc = 0.f;
            const int e_beg = sp * 32;
            const int e_end = min(e_beg + 32, ne);
            for (int e = e_beg; e < e_end; e++) {
                const float f = fb[e * FB_STR + ch];
                const int j = ejs[e];
                const int s = ess[e];
                const float m = __ldg(&AFp[(size_t)j * D_DIM + ch]) * f;
                if (s != cur) {
                    if (cur >= 0) atomicAdd(&Op[(size_t)cur * D_DIM + ch], acc);
                    cur = s; acc = m;
                } else acc += m;
            }
            if (cur >= 0) atomicAdd(&Op[(size_t)cur * D_DIM + ch], acc);
        }
        __syncthreads();   // fbuf free before next tile's A1 writes (overlay)
    }
}

extern "C" void kernel_launch(void* const* d_in, const int* in_sizes, int n_in,
                              void* d_out, int out_size) {
    // order: atom_features, distances, idx_j, seg_i, centers, gamma, W1, b1, W2, b2
    const float* AF      = (const float*)d_in[0];
    const float* dist    = (const float*)d_in[1];
    const int*   idx_j   = (const int*)  d_in[2];
    const int*   seg_i   = (const int*)  d_in[3];
    const float* centers = (const float*)d_in[4];
    const float* gamma   = (const float*)d_in[5];
    const float* W1      = (const float*)d_in[6];
    const float* b1      = (const float*)d_in[7];
    const float* W2      = (const float*)d_in[8];
    const float* b2      = (const float*)d_in[9];
    float* out = (float*)d_out;

    const int E = in_sizes[2];
    const int B = in_sizes[1] / E;
    const int D = in_sizes[7];              // 128
    const int N = in_sizes[0] / (B * D);

    zero_out_kernel<<<2048, 256>>>(out, (size_t)out_size);

    cudaFuncSetAttribute(cfconv_mma_kernel,
                         cudaFuncAttributeMaxDynamicSharedMemorySize, SMEM_TOTAL);
    cfconv_mma_kernel<<<148, THREADS, SMEM_TOTAL>>>(
        AF, dist, idx_j, seg_i, W1, b1, W2, b2, centers, gamma, out, B, N, E);
}

// round 6
// speedup vs baseline: 6.3701x; 1.4114x over previous
#include <cuda_runtime.h>
#include <cuda_bf16.h>
#include <cstdint>

#define THREADS 512
#define TILE_M  128
#define D_DIM   128
#define K_RBF   64

// strides in bf16 elements
#define W_STR   136      // 128 + 8 pad
#define A1_STR  72       // 64 + 8 pad
#define A2_STR  136
#define FB_STR  130      // floats per fbuf row

// ---------------- smem layout (bytes) ----------------
#define OFF_W1HI 0
#define OFF_W1LO (OFF_W1HI + K_RBF * W_STR * 2)       // 17408
#define OFF_W2HI (OFF_W1LO + K_RBF * W_STR * 2)       // 34816
#define OFF_W2LO (OFF_W2HI + D_DIM * W_STR * 2)       // 69632
#define OFF_A1HI (OFF_W2LO + D_DIM * W_STR * 2)       // 104448
#define OFF_A1LO (OFF_A1HI + TILE_M * A1_STR * 2)     // 122880
#define OFF_A2HI (OFF_A1LO + TILE_M * A1_STR * 2)     // 141312
#define OFF_A2LO (OFF_A2HI + TILE_M * A2_STR * 2)     // 176128
#define OFF_FBUF OFF_A1HI                              // overlay (guarded by syncs)
#define OFF_B1S  (OFF_A2LO + TILE_M * A2_STR * 2)     // 210944
#define OFF_B2S  (OFF_B1S + 512)
#define OFF_CEN  (OFF_B2S + 512)
#define OFF_GAM  (OFF_CEN + 256)
#define OFF_EJ   (OFF_GAM + 256)
#define OFF_ES   (OFF_EJ + 512)
#define SMEM_TOTAL (OFF_ES + 512)                      // 213504

// ---------------- PTX helpers ----------------
static __device__ __forceinline__ uint32_t smem_u32(const void* p) {
    uint32_t a;
    asm("{ .reg .u64 t; cvta.to.shared.u64 t, %1; cvt.u32.u64 %0, t; }" : "=r"(a) : "l"(p));
    return a;
}

#define LDSM_X4(r, addr)                                                     \
    asm volatile("ldmatrix.sync.aligned.m8n8.x4.shared.b16 {%0,%1,%2,%3}, [%4];" \
        : "=r"((r)[0]), "=r"((r)[1]), "=r"((r)[2]), "=r"((r)[3]) : "r"(addr))

#define LDSM_X2T(r, addr)                                                    \
    asm volatile("ldmatrix.sync.aligned.m8n8.x2.trans.shared.b16 {%0,%1}, [%2];" \
        : "=r"((r)[0]), "=r"((r)[1]) : "r"(addr))

#define MMA_BF16(c, a, b)                                                    \
    asm volatile("mma.sync.aligned.m16n8k16.row.col.f32.bf16.bf16.f32 "     \
        "{%0,%1,%2,%3}, {%4,%5,%6,%7}, {%8,%9}, {%0,%1,%2,%3};"             \
        : "+f"((c)[0]), "+f"((c)[1]), "+f"((c)[2]), "+f"((c)[3])            \
        : "r"((a)[0]), "r"((a)[1]), "r"((a)[2]), "r"((a)[3]),               \
          "r"((b)[0]), "r"((b)[1]))

static __device__ __forceinline__ float ssp(float x) {
    return fmaxf(x, 0.f) + __logf(1.f + __expf(-fabsf(x))) - 0.69314718055994531f;
}

static __device__ __forceinline__ void bf16_split(float f, uint16_t& hi, uint16_t& lo) {
    __nv_bfloat16 h = __float2bfloat16(f);
    float r = f - __bfloat162float(h);
    __nv_bfloat16 l = __float2bfloat16(r);
    hi = *reinterpret_cast<uint16_t*>(&h);
    lo = *reinterpret_cast<uint16_t*>(&l);
}

__global__ void zero_out_kernel(float* __restrict__ out, size_t n) {
    size_t i = (size_t)blockIdx.x * blockDim.x + threadIdx.x;
    size_t stride = (size_t)gridDim.x * blockDim.x;
    for (; i < n; i += stride) out[i] = 0.f;
}

extern __shared__ char smem[];

__global__ void __launch_bounds__(THREADS, 1)
cfconv_mma_kernel(const float* __restrict__ AF,     // [B,N,D]
                  const float* __restrict__ dist,   // [B,E]
                  const int*   __restrict__ idx_j,  // [E]
                  const int*   __restrict__ seg_i,  // [E] sorted
                  const float* __restrict__ W1,     // [K,D]
                  const float* __restrict__ b1,
                  const float* __restrict__ W2,     // [D,D]
                  const float* __restrict__ b2,
                  const float* __restrict__ centers,
                  const float* __restrict__ gamma,
                  float* __restrict__ out,          // [B,N,D]
                  int B, int N, int E)
{
    const uint32_t sb = smem_u32(smem);
    const int tid  = threadIdx.x;
    const int w    = tid >> 5;
    const int lane = tid & 31;

    float* b1s = (float*)(smem + OFF_B1S);
    float* b2s = (float*)(smem + OFF_B2S);
    float* cen = (float*)(smem + OFF_CEN);
    float* gam = (float*)(smem + OFF_GAM);
    int*   ejs = (int*)  (smem + OFF_EJ);
    int*   ess = (int*)  (smem + OFF_ES);
    float* fb  = (float*)(smem + OFF_FBUF);

    // ---- weight prep: bf16 hi/lo, padded row-major [K][D] ----
    for (int i = tid; i < K_RBF * D_DIM; i += THREADS) {
        const int k = i >> 7, d = i & 127;
        uint16_t hi, lo; bf16_split(W1[i], hi, lo);
        *(uint16_t*)(smem + OFF_W1HI + (k * W_STR + d) * 2) = hi;
        *(uint16_t*)(smem + OFF_W1LO + (k * W_STR + d) * 2) = lo;
    }
    for (int i = tid; i < D_DIM * D_DIM; i += THREADS) {
        const int k = i >> 7, d = i & 127;
        uint16_t hi, lo; bf16_split(W2[i], hi, lo);
        *(uint16_t*)(smem + OFF_W2HI + (k * W_STR + d) * 2) = hi;
        *(uint16_t*)(smem + OFF_W2LO + (k * W_STR + d) * 2) = lo;
    }
    if (tid < D_DIM) { b1s[tid] = b1[tid]; b2s[tid] = b2[tid]; }
    if (tid >= 128 && tid < 128 + K_RBF) {
        const int k = tid - 128; cen[k] = centers[k]; gam[k] = gamma[k];
    }
    __syncthreads();

    // warp tiling: 4x4 warp grid, each warp owns 32 edges x 32 cols
    const int wm = w & 3;
    const int wn = w >> 2;
    const int r0 = wm * 32;
    const int d0 = wn * 32;
    const int arow = lane & 15;
    const int acol = (lane >> 4) * 8;
    const int gr   = lane >> 2;
    const int cc   = (lane & 3) * 2;

    const int tiles_pb = (E + TILE_M - 1) / TILE_M;
    const int total    = B * tiles_pb;

    for (int g = blockIdx.x; g < total; g += gridDim.x) {
        const int b  = g / tiles_pb;
        const int e0 = (g - b * tiles_pb) * TILE_M;
        const int ne = min(TILE_M, E - e0);
        const float* db = dist + (size_t)b * E;

        // -------- Phase A: RBF -> A1 (bf16 hi/lo), meta --------
        {
            const int el = tid >> 2;              // edge 0..127
            const int k0 = (tid & 3) * 16;        // 16 rbf per thread
            const int eg = e0 + min(el, ne - 1);
            const float dv = __ldg(&db[eg]);
            #pragma unroll
            for (int kk = 0; kk < 16; kk += 2) {
                const int k = k0 + kk;
                const float t0 = dv - cen[k];
                const float t1 = dv - cen[k + 1];
                const float v0 = __expf(-gam[k]     * t0 * t0);
                const float v1 = __expf(-gam[k + 1] * t1 * t1);
                uint16_t h0, l0, h1, l1;
                bf16_split(v0, h0, l0);
                bf16_split(v1, h1, l1);
                const uint32_t byt = (uint32_t)(el * A1_STR + k) * 2;
                *(uint32_t*)(smem + OFF_A1HI + byt) = ((uint32_t)h1 << 16) | h0;
                *(uint32_t*)(smem + OFF_A1LO + byt) = ((uint32_t)l1 << 16) | l0;
            }
            if (tid < TILE_M) {
                const int e = e0 + min(tid, ne - 1);
                ejs[tid] = __ldg(&idx_j[e]);
                ess[tid] = __ldg(&seg_i[e]);
            }
        }
        __syncthreads();

        float c[2][4][4];
        #pragma unroll
        for (int mt = 0; mt < 2; mt++)
            #pragma unroll
            for (int nt = 0; nt < 4; nt++)
                { c[mt][nt][0]=0.f; c[mt][nt][1]=0.f; c[mt][nt][2]=0.f; c[mt][nt][3]=0.f; }

        // -------- GEMM1: [32x64] x W1[:,d0:d0+32] --------
        #pragma unroll
        for (int k = 0; k < 4; k++) {
            uint32_t ah[2][4], al[2][4];
            #pragma unroll
            for (int mt = 0; mt < 2; mt++) {
                const uint32_t ab = (uint32_t)((r0 + mt*16 + arow) * A1_STR + k*16 + acol) * 2;
                LDSM_X4(ah[mt], sb + OFF_A1HI + ab);
                LDSM_X4(al[mt], sb + OFF_A1LO + ab);
            }
            const uint32_t brow = (uint32_t)((k*16 + arow) * W_STR) * 2;
            #pragma unroll
            for (int nt = 0; nt < 4; nt++) {
                uint32_t bh[2], bl[2];
                const uint32_t bb = brow + (uint32_t)(d0 + nt*8) * 2;
                LDSM_X2T(bh, sb + OFF_W1HI + bb);
                LDSM_X2T(bl, sb + OFF_W1LO + bb);
                #pragma unroll
                for (int mt = 0; mt < 2; mt++) {
                    MMA_BF16(c[mt][nt], ah[mt], bh);
                    MMA_BF16(c[mt][nt], al[mt], bh);
                    MMA_BF16(c[mt][nt], ah[mt], bl);
                }
            }
        }

        // -------- Epilogue 1: +b1, ssp, split -> A2 --------
        #pragma unroll
        for (int mt = 0; mt < 2; mt++) {
            #pragma unroll
            for (int nt = 0; nt < 4; nt++) {
                const int col = d0 + nt*8 + cc;
                const float f0 = ssp(c[mt][nt][0] + b1s[col]);
                const float f1 = ssp(c[mt][nt][1] + b1s[col + 1]);
                const float f2 = ssp(c[mt][nt][2] + b1s[col]);
                const float f3 = ssp(c[mt][nt][3] + b1s[col + 1]);
                uint16_t h0,l0,h1,l1,h2,l2,h3,l3;
                bf16_split(f0,h0,l0); bf16_split(f1,h1,l1);
                bf16_split(f2,h2,l2); bf16_split(f3,h3,l3);
                const uint32_t r0b = (uint32_t)((r0 + mt*16 + gr)     * A2_STR + col) * 2;
                const uint32_t r1b = (uint32_t)((r0 + mt*16 + gr + 8) * A2_STR + col) * 2;
                *(uint32_t*)(smem + OFF_A2HI + r0b) = ((uint32_t)h1 << 16) | h0;
                *(uint32_t*)(smem + OFF_A2LO + r0b) = ((uint32_t)l1 << 16) | l0;
                *(uint32_t*)(smem + OFF_A2HI + r1b) = ((uint32_t)h3 << 16) | h2;
                *(uint32_t*)(smem + OFF_A2LO + r1b) = ((uint32_t)l3 << 16) | l2;
                c[mt][nt][0]=0.f; c[mt][nt][1]=0.f; c[mt][nt][2]=0.f; c[mt][nt][3]=0.f;
            }
        }
        __syncthreads();

        // -------- GEMM2: [32x128] x W2[:,d0:d0+32] --------
        #pragma unroll
        for (int k = 0; k < 8; k++) {
            uint32_t ah[2][4], al[2][4];
            #pragma unroll
            for (int mt = 0; mt < 2; mt++) {
                const uint32_t ab = (uint32_t)((r0 + mt*16 + arow) * A2_STR + k*16 + acol) * 2;
                LDSM_X4(ah[mt], sb + OFF_A2HI + ab);
                LDSM_X4(al[mt], sb + OFF_A2LO + ab);
            }
            const uint32_t brow = (uint32_t)((k*16 + arow) * W_STR) * 2;
            #pragma unroll
            for (int nt = 0; nt < 4; nt++) {
                uint32_t bh[2], bl[2];
                const uint32_t bb = brow + (uint32_t)(d0 + nt*8) * 2;
                LDSM_X2T(bh, sb + OFF_W2HI + bb);
                LDSM_X2T(bl, sb + OFF_W2LO + bb);
                #pragma unroll
                for (int mt = 0; mt < 2; mt++) {
                    MMA_BF16(c[mt][nt], ah[mt], bh);
                    MMA_BF16(c[mt][nt], al[mt], bh);
                    MMA_BF16(c[mt][nt], ah[mt], bl);
                }
            }
        }
        __syncthreads();   // all warps done with A1/A2 before fbuf overlay writes

        // -------- Epilogue 2: +b2, ssp -> fbuf (fp32) --------
        #pragma unroll
        for (int mt = 0; mt < 2; mt++) {
            #pragma unroll
            for (int nt = 0; nt < 4; nt++) {
                const int col = d0 + nt*8 + cc;
                const float f0 = ssp(c[mt][nt][0] + b2s[col]);
                const float f1 = ssp(c[mt][nt][1] + b2s[col + 1]);
                const float f2 = ssp(c[mt][nt][2] + b2s[col]);
                const float f3 = ssp(c[mt][nt][3] + b2s[col + 1]);
                *(float2*)&fb[(r0 + mt*16 + gr)     * FB_STR + col] = make_float2(f0, f1);
                *(float2*)&fb[(r0 + mt*16 + gr + 8) * FB_STR + col] = make_float2(f2, f3);
            }
        }
        __syncthreads();

        // -------- Gather + sorted segment-sum (batched, MLP=8) --------
        {
            const int ch = tid & 127;
            const int sp = tid >> 7;            // 0..3
            const float* AFp = AF + (size_t)b * N * D_DIM;
            float*       Op  = out + (size_t)b * N * D_DIM;
            int cur = -1; float acc = 0.f;
            const int e_beg = sp * 32;

            if (ne == TILE_M) {
                // fast path: 4 chunks of 8, loads batched for MLP
                #pragma unroll
                for (int chk = 0; chk < 4; chk++) {
                    const int eb = e_beg + chk * 8;
                    float m[8]; int sr[8];
                    #pragma unroll
                    for (int e = 0; e < 8; e++) {
                        const int j = ejs[eb + e];
                        sr[e] = ess[eb + e];
                        m[e] = __ldg(&AFp[(size_t)j * D_DIM + ch]) * fb[(eb + e) * FB_STR + ch];
                    }
                    #pragma unroll
                    for (int e = 0; e < 8; e++) {
                        if (sr[e] != cur) {
                            if (cur >= 0) atomicAdd(&Op[(size_t)cur * D_DIM + ch], acc);
                            cur = sr[e]; acc = m[e];
                        } else acc += m[e];
                    }
                }
            } else {
                const int e_end = min(e_beg + 32, ne);
                for (int e = e_beg; e < e_end; e++) {
                    const float f = fb[e * FB_STR + ch];
                    const int j = ejs[e];
                    const int s = ess[e];
                    const float m = __ldg(&AFp[(size_t)j * D_DIM + ch]) * f;
                    if (s != cur) {
                        if (cur >= 0) atomicAdd(&Op[(size_t)cur * D_DIM + ch], acc);
                        cur = s; acc = m;
                    } else acc += m;
                }
            }
            if (cur >= 0) atomicAdd(&Op[(size_t)cur * D_DIM + ch], acc);
        }
        __syncthreads();   // fbuf free before next tile's A1 writes (overlay)
    }
}

extern "C" void kernel_launch(void* const* d_in, const int* in_sizes, int n_in,
                              void* d_out, int out_size) {
    // order: atom_features, distances, idx_j, seg_i, centers, gamma, W1, b1, W2, b2
    const float* AF      = (const float*)d_in[0];
    const float* dist    = (const float*)d_in[1];
    const int*   idx_j   = (const int*)  d_in[2];
    const int*   seg_i   = (const int*)  d_in[3];
    const float* centers = (const float*)d_in[4];
    const float* gamma   = (const float*)d_in[5];
    const float* W1      = (const float*)d_in[6];
    const float* b1      = (const float*)d_in[7];
    const float* W2      = (const float*)d_in[8];
    const float* b2      = (const float*)d_in[9];
    float* out = (float*)d_out;

    const int E = in_sizes[2];
    const int B = in_sizes[1] / E;
    const int D = in_sizes[7];              // 128
    const int N = in_sizes[0] / (B * D);

    zero_out_kernel<<<2048, 256>>>(out, (size_t)out_size);

    cudaFuncSetAttribute(cfconv_mma_kernel,
                         cudaFuncAttributeMaxDynamicSharedMemorySize, SMEM_TOTAL);
    cfconv_mma_kernel<<<148, THREADS, SMEM_TOTAL>>>(
        AF, dist, idx_j, seg_i, W1, b1, W2, b2, centers, gamma, out, B, N, E);
}